// round 1
// baseline (speedup 1.0000x reference)
#include <cuda_runtime.h>
#include <math.h>

#define TILE 16
#define MAX_G 2048
#define MAX_TILES 4096
#define MAH_CUT 37.0f   // density threshold ~ exp(-18.5) ~ 9e-9

// ---- device scratch (no allocations allowed) ----
__device__ int    g_rank[MAX_G];
__device__ float4 g_packA[MAX_G];   // mx, my, -0.5*iA, -iB   (exp coefficients pre-folded)
__device__ float4 g_packB[MAX_G];   // -0.5*iC, opacity, colR, colG
__device__ float  g_packC[MAX_G];   // colB
__device__ float  g_r2v[MAX_G];     // cull radius^2 = MAH_CUT * lambda_max
__device__ int    g_tile_list[MAX_TILES * MAX_G];
__device__ int    g_tile_count[MAX_TILES];

// ---- 1) stable rank (== argsort position) by depth, O(G^2) ----
__global__ void sort_rank_kernel(const float* __restrict__ depth, int G) {
    __shared__ float sd[MAX_G];
    for (int i = threadIdx.x; i < G; i += blockDim.x) sd[i] = depth[i];
    __syncthreads();
    int i = blockIdx.x * blockDim.x + threadIdx.x;
    if (i >= G) return;
    float di = sd[i];
    int r = 0;
#pragma unroll 8
    for (int j = 0; j < G; j++) {
        float dj = sd[j];
        r += (dj < di) || (dj == di && j < i);
    }
    g_rank[i] = r;
}

// ---- 2) per-gaussian preprocess, scatter into depth-sorted slots ----
__global__ void preprocess_kernel(const float* __restrict__ means,
                                  const float* __restrict__ log_scale,
                                  const float* __restrict__ rot,
                                  const float* __restrict__ colour_logits,
                                  const float* __restrict__ opacity_logit,
                                  int G) {
    int i = blockIdx.x * blockDim.x + threadIdx.x;
    if (i >= G) return;

    float s2x = __expf(2.f * log_scale[2 * i + 0]);
    float s2y = __expf(2.f * log_scale[2 * i + 1]);
    float s, c;
    __sincosf(rot[i], &s, &c);

    float ca = c * c * s2x + s * s * s2y;     // cov[0,0]
    float cb = c * s * (s2x - s2y);           // cov[0,1]
    float cd = s * s * s2x + c * c * s2y;     // cov[1,1]
    float det = ca * cd - cb * cb;
    float inv = 1.f / det;
    float iA = cd * inv;
    float iB = -cb * inv;
    float iC = ca * inv;

    float opac = 1.f / (1.f + __expf(-opacity_logit[i]));
    float cr = 1.f / (1.f + __expf(-colour_logits[3 * i + 0]));
    float cg = 1.f / (1.f + __expf(-colour_logits[3 * i + 1]));
    float cbl = 1.f / (1.f + __expf(-colour_logits[3 * i + 2]));

    // lambda_max of cov: tr +- sqrt(tr^2 - det), tr = (a+d)/2
    float tr = 0.5f * (ca + cd);
    float lmax = tr + sqrtf(fmaxf(tr * tr - det, 0.f));

    int r = g_rank[i];
    g_packA[r] = make_float4(means[2 * i + 0], means[2 * i + 1], -0.5f * iA, -iB);
    g_packB[r] = make_float4(-0.5f * iC, opac, cr, cg);
    g_packC[r] = cbl;
    g_r2v[r]   = MAH_CUT * lmax;
}

// ---- 3) binning: warp per tile, ordered ballot compaction ----
__global__ void binning_kernel(int G, int ntx, int ntiles) {
    int gwarp = (blockIdx.x * blockDim.x + threadIdx.x) >> 5;
    int lane = threadIdx.x & 31;
    if (gwarp >= ntiles) return;

    float x0 = (float)((gwarp % ntx) * TILE);
    float y0 = (float)((gwarp / ntx) * TILE);
    float x1 = x0 + (float)(TILE - 1);
    float y1 = y0 + (float)(TILE - 1);

    int* list = g_tile_list + (size_t)gwarp * MAX_G;
    int cnt = 0;
    for (int base = 0; base < G; base += 32) {
        int g = base + lane;
        bool hit = false;
        if (g < G) {
            float4 A = g_packA[g];
            // point-to-AABB distance from gaussian mean to tile pixel box
            float ddx = fmaxf(fmaxf(x0 - A.x, A.x - x1), 0.f);
            float ddy = fmaxf(fmaxf(y0 - A.y, A.y - y1), 0.f);
            hit = (ddx * ddx + ddy * ddy) <= g_r2v[g];
        }
        unsigned m = __ballot_sync(0xffffffffu, hit);
        if (hit) list[cnt + __popc(m & ((1u << lane) - 1u))] = g;
        cnt += __popc(m);
    }
    if (lane == 0) g_tile_count[gwarp] = cnt;
}

// ---- 4) rasterize: block per 16x16 tile, front-to-back composite ----
__global__ void __launch_bounds__(256) raster_kernel(int W, int H, int ntx,
                                                     float* __restrict__ out) {
    int tile = blockIdx.x;
    int tx = tile % ntx, ty = tile / ntx;
    int lx = threadIdx.x & (TILE - 1);
    int ly = threadIdx.x >> 4;
    int px = tx * TILE + lx;
    int py = ty * TILE + ly;
    float fx = (float)px, fy = (float)py;

    float T = 1.f, accR = 0.f, accG = 0.f, accB = 0.f;

    int n = g_tile_count[tile];
    const int* list = g_tile_list + (size_t)tile * MAX_G;

    __shared__ float4 sA[256];
    __shared__ float4 sB[256];
    __shared__ float  sC[256];

    for (int base = 0; base < n; base += 256) {
        int k = base + threadIdx.x;
        if (k < n) {
            int g = list[k];
            sA[threadIdx.x] = g_packA[g];
            sB[threadIdx.x] = g_packB[g];
            sC[threadIdx.x] = g_packC[g];
        }
        __syncthreads();
        int cnt = min(256, n - base);
        for (int j = 0; j < cnt; j++) {
            float4 A = sA[j];
            float4 B = sB[j];
            float dx = fx - A.x;
            float dy = fy - A.y;
            float e = A.z * dx * dx + A.w * dx * dy + B.x * dy * dy; // = -0.5*mah
            float alpha = B.y * __expf(e);
            alpha = fminf(alpha, 0.99f);
            float w = T * alpha;
            accR = fmaf(w, B.z, accR);
            accG = fmaf(w, B.w, accG);
            accB = fmaf(w, sC[j], accB);
            T = T - w;   // T * (1 - alpha)
        }
        // barrier before shared reuse; also block-uniform early-out
        if (__syncthreads_count(T > 1e-5f) == 0) break;
    }

    if (px < W && py < H) {
        int o = (py * W + px) * 3;
        out[o + 0] = accR;
        out[o + 1] = accG;
        out[o + 2] = accB;
    }
}

extern "C" void kernel_launch(void* const* d_in, const int* in_sizes, int n_in,
                              void* d_out, int out_size) {
    const float* means         = (const float*)d_in[0];
    const float* log_scale     = (const float*)d_in[1];
    const float* rot           = (const float*)d_in[2];
    const float* colour_logits = (const float*)d_in[3];
    const float* opacity_logit = (const float*)d_in[4];
    const float* depth         = (const float*)d_in[5];

    int G = in_sizes[5];
    if (G > MAX_G) G = MAX_G;

    int HW = out_size / 3;
    int W = (int)(sqrt((double)HW) + 0.5);
    if (W <= 0) W = 1;
    int H = HW / W;

    int ntx = (W + TILE - 1) / TILE;
    int nty = (H + TILE - 1) / TILE;
    int ntiles = ntx * nty;

    sort_rank_kernel<<<(G + 127) / 128, 128>>>(depth, G);
    preprocess_kernel<<<(G + 127) / 128, 128>>>(means, log_scale, rot,
                                                colour_logits, opacity_logit, G);
    binning_kernel<<<(ntiles * 32 + 255) / 256, 256>>>(G, ntx, ntiles);
    raster_kernel<<<ntiles, 256>>>(W, H, ntx, (float*)d_out);
}

// round 2
// speedup vs baseline: 1.3261x; 1.3261x over previous
#include <cuda_runtime.h>
#include <math.h>

#define TILE 16
#define MAX_G 2048
#define MAH_CUT 37.0f   // density threshold ~ exp(-18.5) ~ 9e-9

// ---- device scratch (depth-sorted, packed) ----
__device__ float4 g_packA[MAX_G];   // mx, my, -0.5*iA, -iB
__device__ float4 g_packB[MAX_G];   // -0.5*iC, opacity, colR, colG
__device__ float  g_packC[MAX_G];   // colB
__device__ float  g_r2v[MAX_G];     // cull radius^2 = MAH_CUT * lambda_max

// ---- 1) fused: stable rank by depth (O(G) scan/thread) + preprocess + scatter ----
__global__ void prep_kernel(const float* __restrict__ means,
                            const float* __restrict__ log_scale,
                            const float* __restrict__ rot,
                            const float* __restrict__ colour_logits,
                            const float* __restrict__ opacity_logit,
                            const float* __restrict__ depth,
                            int G) {
    __shared__ float sd[MAX_G];
    for (int i = threadIdx.x; i < G; i += blockDim.x) sd[i] = depth[i];
    // pad so float4 reads are safe
    for (int i = G + threadIdx.x; i < ((G + 3) & ~3); i += blockDim.x) sd[i] = 3.0e38f;
    __syncthreads();

    int i = blockIdx.x * blockDim.x + threadIdx.x;
    if (i >= G) return;
    float di = sd[i];

    int r = 0;
    int G4 = (G + 3) >> 2;
    const float4* sd4 = (const float4*)sd;
#pragma unroll 4
    for (int j4 = 0; j4 < G4; j4++) {
        float4 d = sd4[j4];
        int j = j4 * 4;
        r += (d.x < di) || (d.x == di && (j + 0) < i);
        r += (d.y < di) || (d.y == di && (j + 1) < i);
        r += (d.z < di) || (d.z == di && (j + 2) < i);
        r += (d.w < di) || (d.w == di && (j + 3) < i);
    }

    float s2x = __expf(2.f * log_scale[2 * i + 0]);
    float s2y = __expf(2.f * log_scale[2 * i + 1]);
    float s, c;
    __sincosf(rot[i], &s, &c);

    float ca = c * c * s2x + s * s * s2y;
    float cb = c * s * (s2x - s2y);
    float cd = s * s * s2x + c * c * s2y;
    float det = ca * cd - cb * cb;
    float inv = 1.f / det;
    float iA = cd * inv;
    float iB = -cb * inv;
    float iC = ca * inv;

    float opac = 1.f / (1.f + __expf(-opacity_logit[i]));
    float cr  = 1.f / (1.f + __expf(-colour_logits[3 * i + 0]));
    float cg  = 1.f / (1.f + __expf(-colour_logits[3 * i + 1]));
    float cbl = 1.f / (1.f + __expf(-colour_logits[3 * i + 2]));

    float tr = 0.5f * (ca + cd);
    float lmax = tr + sqrtf(fmaxf(tr * tr - det, 0.f));

    g_packA[r] = make_float4(means[2 * i + 0], means[2 * i + 1], -0.5f * iA, -iB);
    g_packB[r] = make_float4(-0.5f * iC, opac, cr, cg);
    g_packC[r] = cbl;
    g_r2v[r]   = MAH_CUT * lmax;
}

// ---- 2) raster: block per 16x16 tile; in-block ordered cull+compact, composite ----
__global__ void __launch_bounds__(256) raster_kernel(int W, int H, int ntx, int G,
                                                     float* __restrict__ out) {
    int tile = blockIdx.x;
    int tx = tile % ntx, ty = tile / ntx;
    int lx = threadIdx.x & (TILE - 1);
    int ly = threadIdx.x >> 4;
    int px = tx * TILE + lx;
    int py = ty * TILE + ly;
    float fx = (float)px, fy = (float)py;

    // tile pixel box for culling
    float x0 = (float)(tx * TILE);
    float y0 = (float)(ty * TILE);
    float x1 = x0 + (float)(TILE - 1);
    float y1 = y0 + (float)(TILE - 1);

    int wid  = threadIdx.x >> 5;
    int lane = threadIdx.x & 31;

    float T = 1.f, accR = 0.f, accG = 0.f, accB = 0.f;

    __shared__ float4 sA[256];
    __shared__ float4 sB[256];
    __shared__ float  sC[256];
    __shared__ int    swcnt[8];

    for (int base = 0; base < G; base += 256) {
        int g = base + threadIdx.x;
        bool hit = false;
        float4 A;
        if (g < G) {
            A = g_packA[g];
            float ddx = fmaxf(fmaxf(x0 - A.x, A.x - x1), 0.f);
            float ddy = fmaxf(fmaxf(y0 - A.y, A.y - y1), 0.f);
            hit = (ddx * ddx + ddy * ddy) <= g_r2v[g];
        }
        unsigned m = __ballot_sync(0xffffffffu, hit);
        if (lane == 0) swcnt[wid] = __popc(m);
        __syncthreads();
        int woff = 0, total = 0;
#pragma unroll
        for (int w = 0; w < 8; w++) {
            int cw = swcnt[w];
            woff += (w < wid) ? cw : 0;
            total += cw;
        }
        // overwrite barrier: swcnt reads done, sA/sB/sC from prev chunk consumed
        __syncthreads();
        if (hit) {
            int idx = woff + __popc(m & ((1u << lane) - 1u));
            sA[idx] = A;
            sB[idx] = g_packB[g];
            sC[idx] = g_packC[g];
        }
        __syncthreads();

        for (int j = 0; j < total; j++) {
            float4 Aj = sA[j];
            float4 Bj = sB[j];
            float dx = fx - Aj.x;
            float dy = fy - Aj.y;
            float e = Aj.z * dx * dx + Aj.w * dx * dy + Bj.x * dy * dy; // -0.5*mah
            float alpha = fminf(Bj.y * __expf(e), 0.99f);
            float w = T * alpha;
            accR = fmaf(w, Bj.z, accR);
            accG = fmaf(w, Bj.w, accG);
            accB = fmaf(w, sC[j], accB);
            T = T - w;
        }
        // early-out when whole tile is saturated (also serves as loop barrier)
        if (__syncthreads_count(T > 1e-5f) == 0) break;
    }

    if (px < W && py < H) {
        int o = (py * W + px) * 3;
        out[o + 0] = accR;
        out[o + 1] = accG;
        out[o + 2] = accB;
    }
}

extern "C" void kernel_launch(void* const* d_in, const int* in_sizes, int n_in,
                              void* d_out, int out_size) {
    const float* means         = (const float*)d_in[0];
    const float* log_scale     = (const float*)d_in[1];
    const float* rot           = (const float*)d_in[2];
    const float* colour_logits = (const float*)d_in[3];
    const float* opacity_logit = (const float*)d_in[4];
    const float* depth         = (const float*)d_in[5];

    int G = in_sizes[5];
    if (G > MAX_G) G = MAX_G;

    int HW = out_size / 3;
    int W = (int)(sqrt((double)HW) + 0.5);
    if (W <= 0) W = 1;
    int H = HW / W;

    int ntx = (W + TILE - 1) / TILE;
    int nty = (H + TILE - 1) / TILE;
    int ntiles = ntx * nty;

    prep_kernel<<<(G + 255) / 256, 256>>>(means, log_scale, rot,
                                          colour_logits, opacity_logit, depth, G);
    raster_kernel<<<ntiles, 256>>>(W, H, ntx, G, (float*)d_out);
}

// round 3
// speedup vs baseline: 1.9458x; 1.4673x over previous
#include <cuda_runtime.h>
#include <math.h>

#define TILE 16
#define MAX_G 2048
#define MAH_CUT 37.0f   // density threshold ~ exp(-18.5) ~ 9e-9

// ---- device scratch (depth-sorted, packed) ----
__device__ float4 g_packA[MAX_G];   // mx, my, -0.5*iA, -iB
__device__ float4 g_packB[MAX_G];   // -0.5*iC, opacity, colR, colG
__device__ float  g_packC[MAX_G];   // colB
__device__ float  g_r2v[MAX_G];     // cull radius^2 = MAH_CUT * lambda_max

// ---- 1) prep: warp-per-gaussian stable rank + preprocess + scatter ----
// grid = ceil(G/8) blocks x 256 threads (8 warps); warp w of block b owns
// gaussian i = b*8 + w. Lanes stride the shared depth array, redux-sum the rank.
__global__ void __launch_bounds__(256) prep_kernel(
        const float* __restrict__ means,
        const float* __restrict__ log_scale,
        const float* __restrict__ rot,
        const float* __restrict__ colour_logits,
        const float* __restrict__ opacity_logit,
        const float* __restrict__ depth,
        int G) {
    __shared__ float sd[MAX_G];
    for (int j = threadIdx.x; j < G; j += blockDim.x) sd[j] = depth[j];
    __syncthreads();

    int w    = threadIdx.x >> 5;
    int lane = threadIdx.x & 31;
    int i = blockIdx.x * 8 + w;
    if (i >= G) return;

    float di = sd[i];
    int r = 0;
    for (int j = lane; j < G; j += 32) {
        float dj = sd[j];
        r += (dj < di) || (dj == di && j < i);
    }
    r = __reduce_add_sync(0xffffffffu, r);

    if (lane == 0) {
        float s2x = __expf(2.f * log_scale[2 * i + 0]);
        float s2y = __expf(2.f * log_scale[2 * i + 1]);
        float s, c;
        __sincosf(rot[i], &s, &c);

        float ca = c * c * s2x + s * s * s2y;
        float cb = c * s * (s2x - s2y);
        float cd = s * s * s2x + c * c * s2y;
        float det = ca * cd - cb * cb;
        float inv = 1.f / det;
        float iA = cd * inv;
        float iB = -cb * inv;
        float iC = ca * inv;

        float opac = 1.f / (1.f + __expf(-opacity_logit[i]));
        float cr  = 1.f / (1.f + __expf(-colour_logits[3 * i + 0]));
        float cg  = 1.f / (1.f + __expf(-colour_logits[3 * i + 1]));
        float cbl = 1.f / (1.f + __expf(-colour_logits[3 * i + 2]));

        float tr = 0.5f * (ca + cd);
        float lmax = tr + sqrtf(fmaxf(tr * tr - det, 0.f));

        g_packA[r] = make_float4(means[2 * i + 0], means[2 * i + 1], -0.5f * iA, -iB);
        g_packB[r] = make_float4(-0.5f * iC, opac, cr, cg);
        g_packC[r] = cbl;
        g_r2v[r]   = MAH_CUT * lmax;
    }
}

// ---- 2) raster: block per 16x16 tile, ONE barrier ----
// Each warp culls its own contiguous range of R gaussians into a private
// shared index region (depth order preserved), then after a single barrier
// every warp composites region-by-region with independent early exit.
__global__ void __launch_bounds__(256) raster_kernel(int W, int H, int ntx, int G,
                                                     float* __restrict__ out) {
    int tile = blockIdx.x;
    int tx = tile % ntx, ty = tile / ntx;
    int lx = threadIdx.x & (TILE - 1);
    int ly = threadIdx.x >> 4;
    int px = tx * TILE + lx;
    int py = ty * TILE + ly;
    float fx = (float)px, fy = (float)py;

    float x0 = (float)(tx * TILE);
    float y0 = (float)(ty * TILE);
    float x1 = x0 + (float)(TILE - 1);
    float y1 = y0 + (float)(TILE - 1);

    int wid  = threadIdx.x >> 5;
    int lane = threadIdx.x & 31;

    __shared__ int sIdx[MAX_G];
    __shared__ int scnt[8];

    // per-warp range length, multiple of 32, 8*R >= G
    int R = ((G + 255) >> 8) << 5;
    int gbase = wid * R;
    int cnt = 0;
    for (int r = 0; r < R; r += 32) {
        int g = gbase + r + lane;
        bool hit = false;
        if (g < G) {
            float4 A = g_packA[g];
            float ddx = fmaxf(fmaxf(x0 - A.x, A.x - x1), 0.f);
            float ddy = fmaxf(fmaxf(y0 - A.y, A.y - y1), 0.f);
            hit = (ddx * ddx + ddy * ddy) <= g_r2v[g];
        }
        unsigned m = __ballot_sync(0xffffffffu, hit);
        if (hit) sIdx[gbase + cnt + __popc(m & ((1u << lane) - 1u))] = g;
        cnt += __popc(m);
    }
    if (lane == 0) scnt[wid] = cnt;
    __syncthreads();   // the only block barrier

    float T = 1.f, accR = 0.f, accG = 0.f, accB = 0.f;

    for (int w2 = 0; w2 < 8; w2++) {
        int c = scnt[w2];
        const int* reg = sIdx + w2 * R;
#pragma unroll 2
        for (int j = 0; j < c; j++) {
            int g = reg[j];                 // warp-uniform
            float4 A = g_packA[g];
            float4 B = g_packB[g];
            float Cb = g_packC[g];
            float dx = fx - A.x;
            float dy = fy - A.y;
            float e = A.z * dx * dx + A.w * dx * dy + B.x * dy * dy; // -0.5*mah
            float alpha = fminf(B.y * __expf(e), 0.99f);
            float wgt = T * alpha;
            accR = fmaf(wgt, B.z, accR);
            accG = fmaf(wgt, B.w, accG);
            accB = fmaf(wgt, Cb, accB);
            T = T - wgt;
        }
        // warp-independent early-out (no more shared-mem hazards)
        if (__all_sync(0xffffffffu, T <= 1e-5f)) break;
    }

    if (px < W && py < H) {
        int o = (py * W + px) * 3;
        out[o + 0] = accR;
        out[o + 1] = accG;
        out[o + 2] = accB;
    }
}

extern "C" void kernel_launch(void* const* d_in, const int* in_sizes, int n_in,
                              void* d_out, int out_size) {
    const float* means         = (const float*)d_in[0];
    const float* log_scale     = (const float*)d_in[1];
    const float* rot           = (const float*)d_in[2];
    const float* colour_logits = (const float*)d_in[3];
    const float* opacity_logit = (const float*)d_in[4];
    const float* depth         = (const float*)d_in[5];

    int G = in_sizes[5];
    if (G > MAX_G) G = MAX_G;

    int HW = out_size / 3;
    int W = (int)(sqrt((double)HW) + 0.5);
    if (W <= 0) W = 1;
    int H = HW / W;

    int ntx = (W + TILE - 1) / TILE;
    int nty = (H + TILE - 1) / TILE;
    int ntiles = ntx * nty;

    prep_kernel<<<(G + 7) / 8, 256>>>(means, log_scale, rot,
                                      colour_logits, opacity_logit, depth, G);
    raster_kernel<<<ntiles, 256>>>(W, H, ntx, G, (float*)d_out);
}

// round 4
// speedup vs baseline: 2.2102x; 1.1359x over previous
#include <cuda_runtime.h>
#include <math.h>

#define TILE 16
#define MAX_G 2048
#define CHUNK 1024
#define RPW (CHUNK / 8)      // gaussians per warp per chunk = 128
#define ROUNDS (RPW / 32)    // ballot rounds per warp = 4
#define MAH_CUT 37.0f        // density threshold ~ exp(-18.5) ~ 9e-9

// ---- device scratch (depth-sorted, packed) ----
__device__ float4 g_packA[MAX_G];   // mx, my, -0.5*iA, -iB
__device__ float4 g_packB[MAX_G];   // -0.5*iC, opacity, colR, colG
__device__ float  g_packC[MAX_G];   // colB
__device__ float  g_r2v[MAX_G];     // cull radius^2 = MAH_CUT * lambda_max

// ---- 1) prep: warp-per-gaussian stable rank + preprocess + scatter ----
__global__ void __launch_bounds__(256) prep_kernel(
        const float* __restrict__ means,
        const float* __restrict__ log_scale,
        const float* __restrict__ rot,
        const float* __restrict__ colour_logits,
        const float* __restrict__ opacity_logit,
        const float* __restrict__ depth,
        int G) {
    __shared__ float sd[MAX_G];
    for (int j = threadIdx.x; j < G; j += blockDim.x) sd[j] = depth[j];
    __syncthreads();

    int w    = threadIdx.x >> 5;
    int lane = threadIdx.x & 31;
    int i = blockIdx.x * 8 + w;
    if (i >= G) return;

    float di = sd[i];
    int r = 0;
    for (int j = lane; j < G; j += 32) {
        float dj = sd[j];
        r += (dj < di) || (dj == di && j < i);
    }
    r = __reduce_add_sync(0xffffffffu, r);

    if (lane == 0) {
        float s2x = __expf(2.f * log_scale[2 * i + 0]);
        float s2y = __expf(2.f * log_scale[2 * i + 1]);
        float s, c;
        __sincosf(rot[i], &s, &c);

        float ca = c * c * s2x + s * s * s2y;
        float cb = c * s * (s2x - s2y);
        float cd = s * s * s2x + c * c * s2y;
        float det = ca * cd - cb * cb;
        float inv = 1.f / det;
        float iA = cd * inv;
        float iB = -cb * inv;
        float iC = ca * inv;

        float opac = 1.f / (1.f + __expf(-opacity_logit[i]));
        float cr  = 1.f / (1.f + __expf(-colour_logits[3 * i + 0]));
        float cg  = 1.f / (1.f + __expf(-colour_logits[3 * i + 1]));
        float cbl = 1.f / (1.f + __expf(-colour_logits[3 * i + 2]));

        float tr = 0.5f * (ca + cd);
        float lmax = tr + sqrtf(fmaxf(tr * tr - det, 0.f));

        g_packA[r] = make_float4(means[2 * i + 0], means[2 * i + 1], -0.5f * iA, -iB);
        g_packB[r] = make_float4(-0.5f * iC, opac, cr, cg);
        g_packC[r] = cbl;
        g_r2v[r]   = MAH_CUT * lmax;
    }
}

// ---- 2) raster: block per 16x16 tile ----
// Per chunk of up to 1024 gaussians: each warp prefetches its 128-range
// (registers), runs 4 ballot rounds, then all warps scatter compacted
// gaussian DATA into one flat depth-ordered shared list (2 barriers).
// Composite is a single LDS-only loop.
__global__ void __launch_bounds__(256) raster_kernel(int W, int H, int ntx, int G,
                                                     float* __restrict__ out) {
    int tile = blockIdx.x;
    int tx = tile % ntx, ty = tile / ntx;
    int lx = threadIdx.x & (TILE - 1);
    int ly = threadIdx.x >> 4;
    int px = tx * TILE + lx;
    int py = ty * TILE + ly;
    float fx = (float)px, fy = (float)py;

    float x0 = (float)(tx * TILE);
    float y0 = (float)(ty * TILE);
    float x1 = x0 + (float)(TILE - 1);
    float y1 = y0 + (float)(TILE - 1);

    int wid  = threadIdx.x >> 5;
    int lane = threadIdx.x & 31;
    unsigned lmask = (1u << lane) - 1u;

    __shared__ float4 sA[CHUNK];
    __shared__ float4 sB[CHUNK];
    __shared__ float  sC[CHUNK];
    __shared__ int    scnt[8];

    float T = 1.f, accR = 0.f, accG = 0.f, accB = 0.f;

    for (int c0 = 0; c0 < G; c0 += CHUNK) {
        int gw = c0 + wid * RPW;

        // -- prefetch all rounds (independent loads, one latency) --
        float4 Ar[ROUNDS];
        float  r2[ROUNDS];
#pragma unroll
        for (int r = 0; r < ROUNDS; r++) {
            int g = gw + r * 32 + lane;
            bool ok = g < G;
            Ar[r] = ok ? g_packA[g] : make_float4(1e30f, 1e30f, 0.f, 0.f);
            r2[r] = ok ? g_r2v[g] : -1.f;
        }

        // -- ballot rounds on registers --
        unsigned mask[ROUNDS];
        int offr[ROUNDS];
        int cnt = 0;
#pragma unroll
        for (int r = 0; r < ROUNDS; r++) {
            float ddx = fmaxf(fmaxf(x0 - Ar[r].x, Ar[r].x - x1), 0.f);
            float ddy = fmaxf(fmaxf(y0 - Ar[r].y, Ar[r].y - y1), 0.f);
            bool hit = (ddx * ddx + ddy * ddy) <= r2[r];
            mask[r] = __ballot_sync(0xffffffffu, hit);
            offr[r] = cnt;
            cnt += __popc(mask[r]);
        }
        if (lane == 0) scnt[wid] = cnt;
        __syncthreads();   // also orders previous chunk's composite reads

        int woff = 0, total = 0;
#pragma unroll
        for (int w = 0; w < 8; w++) {
            int cw = scnt[w];
            woff += (w < wid) ? cw : 0;
            total += cw;
        }

        // -- scatter compacted data (depth order preserved) --
#pragma unroll
        for (int r = 0; r < ROUNDS; r++) {
            if ((mask[r] >> lane) & 1u) {
                int idx = woff + offr[r] + __popc(mask[r] & lmask);
                int g = gw + r * 32 + lane;
                sA[idx] = Ar[r];
                sB[idx] = g_packB[g];
                sC[idx] = g_packC[g];
            }
        }
        __syncthreads();

        // -- composite: single flat LDS-only loop --
        for (int j = 0; j < total; j++) {
            float4 Aj = sA[j];
            float4 Bj = sB[j];
            float dx = fx - Aj.x;
            float dy = fy - Aj.y;
            float e = Aj.z * dx * dx + Aj.w * dx * dy + Bj.x * dy * dy;
            float alpha = fminf(Bj.y * __expf(e), 0.99f);
            float wgt = T * alpha;
            accR = fmaf(wgt, Bj.z, accR);
            accG = fmaf(wgt, Bj.w, accG);
            accB = fmaf(wgt, sC[j], accB);
            T = T - wgt;
            if ((j & 3) == 3 && __all_sync(0xffffffffu, T <= 1e-5f)) break;
        }
    }

    if (px < W && py < H) {
        int o = (py * W + px) * 3;
        out[o + 0] = accR;
        out[o + 1] = accG;
        out[o + 2] = accB;
    }
}

extern "C" void kernel_launch(void* const* d_in, const int* in_sizes, int n_in,
                              void* d_out, int out_size) {
    const float* means         = (const float*)d_in[0];
    const float* log_scale     = (const float*)d_in[1];
    const float* rot           = (const float*)d_in[2];
    const float* colour_logits = (const float*)d_in[3];
    const float* opacity_logit = (const float*)d_in[4];
    const float* depth         = (const float*)d_in[5];

    int G = in_sizes[5];
    if (G > MAX_G) G = MAX_G;

    int HW = out_size / 3;
    int W = (int)(sqrt((double)HW) + 0.5);
    if (W <= 0) W = 1;
    int H = HW / W;

    int ntx = (W + TILE - 1) / TILE;
    int nty = (H + TILE - 1) / TILE;
    int ntiles = ntx * nty;

    prep_kernel<<<(G + 7) / 8, 256>>>(means, log_scale, rot,
                                      colour_logits, opacity_logit, depth, G);
    raster_kernel<<<ntiles, 256>>>(W, H, ntx, G, (float*)d_out);
}

// round 5
// speedup vs baseline: 2.5515x; 1.1544x over previous
#include <cuda_runtime.h>
#include <math.h>

#define TILE_W 16
#define TILE_H 8
#define NTHREADS 128
#define NW 4                 // warps per block
#define MAX_G 2048
#define CHUNK 512
#define RPW (CHUNK / NW)     // 128 gaussians per warp per chunk
#define ROUNDS (RPW / 32)    // 4 ballot rounds
#define MAH_CUT 37.0f        // density threshold ~ exp(-18.5)
#define LOG2E 1.4426950408889634f

// ---- device scratch (depth-sorted, packed) ----
__device__ float4 g_pA[MAX_G];   // mx, my, cullR^2, a' (= -0.5*iA*log2e)
__device__ float4 g_pB[MAX_G];   // b' (= -iB*log2e), c' (= -0.5*iC*log2e), log2(opac), colR
__device__ float2 g_pC[MAX_G];   // colG, colB

__device__ __forceinline__ float ex2(float x) {
    float r;
    asm("ex2.approx.ftz.f32 %0, %1;" : "=f"(r) : "f"(x));
    return r;
}

// ---- 1) prep: warp-per-gaussian stable rank + preprocess + scatter ----
__global__ void __launch_bounds__(256) prep_kernel(
        const float* __restrict__ means,
        const float* __restrict__ log_scale,
        const float* __restrict__ rot,
        const float* __restrict__ colour_logits,
        const float* __restrict__ opacity_logit,
        const float* __restrict__ depth,
        int G) {
    __shared__ float sd[MAX_G];
    for (int j = threadIdx.x; j < G; j += blockDim.x) sd[j] = depth[j];
    __syncthreads();

    int w    = threadIdx.x >> 5;
    int lane = threadIdx.x & 31;
    int i = blockIdx.x * 8 + w;
    if (i >= G) return;

    float di = sd[i];
    int r = 0;
    for (int j = lane; j < G; j += 32) {
        float dj = sd[j];
        r += (dj < di) || (dj == di && j < i);
    }
    r = __reduce_add_sync(0xffffffffu, r);

    if (lane == 0) {
        float s2x = __expf(2.f * log_scale[2 * i + 0]);
        float s2y = __expf(2.f * log_scale[2 * i + 1]);
        float s, c;
        __sincosf(rot[i], &s, &c);

        float ca = c * c * s2x + s * s * s2y;
        float cb = c * s * (s2x - s2y);
        float cd = s * s * s2x + c * c * s2y;
        float det = ca * cd - cb * cb;
        float inv = 1.f / det;
        float iA = cd * inv;
        float iB = -cb * inv;
        float iC = ca * inv;

        float opac = 1.f / (1.f + __expf(-opacity_logit[i]));
        float cr  = 1.f / (1.f + __expf(-colour_logits[3 * i + 0]));
        float cg  = 1.f / (1.f + __expf(-colour_logits[3 * i + 1]));
        float cbl = 1.f / (1.f + __expf(-colour_logits[3 * i + 2]));

        float tr = 0.5f * (ca + cd);
        float lmax = tr + sqrtf(fmaxf(tr * tr - det, 0.f));

        g_pA[r] = make_float4(means[2 * i + 0], means[2 * i + 1],
                              MAH_CUT * lmax, -0.5f * iA * LOG2E);
        g_pB[r] = make_float4(-iB * LOG2E, -0.5f * iC * LOG2E,
                              __log2f(opac), cr);
        g_pC[r] = make_float2(cg, cbl);
    }
}

// ---- 2) raster: block per 16x8 tile, 128 threads ----
__global__ void __launch_bounds__(NTHREADS) raster_kernel(int W, int H, int ntx, int G,
                                                          float* __restrict__ out) {
    int tile = blockIdx.x;
    int tx = tile % ntx, ty = tile / ntx;
    int lx = threadIdx.x & (TILE_W - 1);
    int ly = threadIdx.x >> 4;
    int px = tx * TILE_W + lx;
    int py = ty * TILE_H + ly;
    float fx = (float)px, fy = (float)py;

    float x0 = (float)(tx * TILE_W);
    float y0 = (float)(ty * TILE_H);
    float x1 = x0 + (float)(TILE_W - 1);
    float y1 = y0 + (float)(TILE_H - 1);

    int wid  = threadIdx.x >> 5;
    int lane = threadIdx.x & 31;
    unsigned lmask = (1u << lane) - 1u;

    __shared__ float4 sA[CHUNK];
    __shared__ float4 sB[CHUNK];
    __shared__ float2 sC[CHUNK];
    __shared__ int    scnt[NW];

    float T = 1.f, accR = 0.f, accG = 0.f, accB = 0.f;

    for (int c0 = 0; c0 < G; c0 += CHUNK) {
        int gw = c0 + wid * RPW;

        // prefetch cull data: one LDG.128 per gaussian
        float4 Ar[ROUNDS];
#pragma unroll
        for (int r = 0; r < ROUNDS; r++) {
            int g = gw + r * 32 + lane;
            Ar[r] = (g < G) ? g_pA[g] : make_float4(1e30f, 1e30f, -1.f, 0.f);
        }

        // hit tests (registers only)
        bool hr[ROUNDS];
#pragma unroll
        for (int r = 0; r < ROUNDS; r++) {
            float ddx = fmaxf(fmaxf(x0 - Ar[r].x, Ar[r].x - x1), 0.f);
            float ddy = fmaxf(fmaxf(y0 - Ar[r].y, Ar[r].y - y1), 0.f);
            hr[r] = (ddx * ddx + ddy * ddy) <= Ar[r].z;
        }

        // issue predicated B/C loads early so latency overlaps prefix math
        float4 Br[ROUNDS];
        float2 Cr[ROUNDS];
#pragma unroll
        for (int r = 0; r < ROUNDS; r++) {
            if (hr[r]) {
                int g = gw + r * 32 + lane;
                Br[r] = g_pB[g];
                Cr[r] = g_pC[g];
            }
        }

        // ballots + in-warp offsets
        unsigned mask[ROUNDS];
        int offr[ROUNDS];
        int cnt = 0;
#pragma unroll
        for (int r = 0; r < ROUNDS; r++) {
            mask[r] = __ballot_sync(0xffffffffu, hr[r]);
            offr[r] = cnt;
            cnt += __popc(mask[r]);
        }
        if (lane == 0) scnt[wid] = cnt;
        __syncthreads();   // also guards prev-chunk composite reads

        int woff = 0, total = 0;
#pragma unroll
        for (int w = 0; w < NW; w++) {
            int cw = scnt[w];
            woff += (w < wid) ? cw : 0;
            total += cw;
        }

        // scatter compacted data (depth order preserved)
#pragma unroll
        for (int r = 0; r < ROUNDS; r++) {
            if (hr[r]) {
                int idx = woff + offr[r] + __popc(mask[r] & lmask);
                sA[idx] = Ar[r];
                sB[idx] = Br[r];
                sC[idx] = Cr[r];
            }
        }
        __syncthreads();

        // flat branch-free composite
#pragma unroll 4
        for (int j = 0; j < total; j++) {
            float4 Aj = sA[j];
            float4 Bj = sB[j];
            float2 Cj = sC[j];
            float dx = fx - Aj.x;
            float dy = fy - Aj.y;
            float e = fmaf(Aj.w, dx * dx,
                      fmaf(Bj.x, dx * dy,
                      fmaf(Bj.y, dy * dy, Bj.z)));
            float alpha = fminf(ex2(e), 0.99f);
            float wgt = T * alpha;
            accR = fmaf(wgt, Bj.w, accR);
            accG = fmaf(wgt, Cj.x, accG);
            accB = fmaf(wgt, Cj.y, accB);
            T = T - wgt;
        }
    }

    if (px < W && py < H) {
        int o = (py * W + px) * 3;
        out[o + 0] = accR;
        out[o + 1] = accG;
        out[o + 2] = accB;
    }
}

extern "C" void kernel_launch(void* const* d_in, const int* in_sizes, int n_in,
                              void* d_out, int out_size) {
    const float* means         = (const float*)d_in[0];
    const float* log_scale     = (const float*)d_in[1];
    const float* rot           = (const float*)d_in[2];
    const float* colour_logits = (const float*)d_in[3];
    const float* opacity_logit = (const float*)d_in[4];
    const float* depth         = (const float*)d_in[5];

    int G = in_sizes[5];
    if (G > MAX_G) G = MAX_G;

    int HW = out_size / 3;
    int W = (int)(sqrt((double)HW) + 0.5);
    if (W <= 0) W = 1;
    int H = HW / W;

    int ntx = (W + TILE_W - 1) / TILE_W;
    int nty = (H + TILE_H - 1) / TILE_H;
    int ntiles = ntx * nty;

    prep_kernel<<<(G + 7) / 8, 256>>>(means, log_scale, rot,
                                      colour_logits, opacity_logit, depth, G);
    raster_kernel<<<ntiles, NTHREADS>>>(W, H, ntx, G, (float*)d_out);
}